// round 10
// baseline (speedup 1.0000x reference)
#include <cuda_runtime.h>
#include <cuda_bf16.h>

// CTC forward, two tasks (PyTorch semantics: blank=0, mean of loss/target_len,
// zero_infinity). One block per (task, batch) = 64 blocks x 128 threads.
//
// Register-blocked wavefront (4 slots/thread, (m,e) extended-float pairs) with
// NO per-step block barrier: warps are decoupled via an 8-byte single-copy-
// atomic handshake ring in shared memory (full depth T -> no wrap, no fences;
// mantissa in [1,2) => lo32 != 0 is the validity sentinel). Symbol probs are
// gathered per-thread from global with a depth-3 register prefetch pipeline.

#define LOG2E 1.4426950408889634f
#define LN2   0.6931471805599453f
#define BATCH 32
#define TMAX  2000
#define NT    128
#define EDEAD (-(1 << 28))
// dynamic smem: sD[TMAX] floats + ring[4][TMAX] uint2
#define DYNSMEM (TMAX * 4 + 4 * TMAX * 8)

static __device__ float        g_partial[64];
static __device__ unsigned int g_count = 0;

__device__ __forceinline__ float ex2(float x) {
    float y; asm("ex2.approx.f32 %0, %1;" : "=f"(y) : "f"(x)); return y;
}
__device__ __forceinline__ float lg2(float x) {
    float y; asm("lg2.approx.f32 %0, %1;" : "=f"(y) : "f"(x)); return y;
}

__device__ __forceinline__ void upd3(float ma, int ea, float mb, int eb,
                                     float mc, int ec, float p,
                                     float& mo, int& eo) {
    int em = max(ea, max(eb, ec));
    float sa = __int_as_float(max(ea - em + 127, 0) << 23);
    float sb = __int_as_float(max(eb - em + 127, 0) << 23);
    float sc = __int_as_float(max(ec - em + 127, 0) << 23);
    float s  = fmaf(mc, sc, fmaf(mb, sb, ma * sa));
    float mp = p * s;
    int bb = __float_as_int(mp);
    eo = em + ((bb >> 23) - 127);
    mo = __int_as_float((bb & 0x007FFFFF) | 0x3F800000);
}
__device__ __forceinline__ void upd2(float ma, int ea, float mb, int eb,
                                     float p, float& mo, int& eo) {
    int em = max(ea, eb);
    float sa = __int_as_float(max(ea - em + 127, 0) << 23);
    float sb = __int_as_float(max(eb - em + 127, 0) << 23);
    float s  = fmaf(mb, sb, ma * sa);
    float mp = p * s;
    int bb = __float_as_int(mp);
    eo = em + ((bb >> 23) - 127);
    mo = __int_as_float((bb & 0x007FFFFF) | 0x3F800000);
}
__device__ __forceinline__ float pow2c(int dp127) {
    return __int_as_float(max(dp127, 0) << 23);
}
__device__ __forceinline__ float clamplp(float x) {  // finite, NaN-safe
    return fminf(fmaxf(x, -120.f), 0.f);
}

__global__ void __launch_bounds__(NT, 1)
ctc_forward_kernel(const float* __restrict__ elog, const float* __restrict__ plog,
                   const int* __restrict__ etgt, const int* __restrict__ ptgt,
                   const int* __restrict__ eil,  const int* __restrict__ pil,
                   const int* __restrict__ etl,  const int* __restrict__ ptl,
                   float* __restrict__ out)
{
    extern __shared__ unsigned char dynsmem[];
    float* sD   = reinterpret_cast<float*>(dynsmem);          // [TMAX]
    uint2* sRing = reinterpret_cast<uint2*>(dynsmem + TMAX * 4); // [4][TMAX]

    __shared__ float sFm[NT * 4];
    __shared__ int   sFe[NT * 4];
    __shared__ int   sLast;

    const int task = blockIdx.x >> 5;   // 0 = error (C=4), 1 = phoneme (C=64)
    const int b    = blockIdx.x & 31;
    const int tid  = threadIdx.x;
    const int lane = tid & 31;
    const int wid  = tid >> 5;

    const float* logits;
    const int*   targets;
    int C, S, ilen, tlen;
    if (task == 0) {
        C = 4;  S = 50;
        logits  = elog + (size_t)b * TMAX * 4;
        targets = etgt + b * 50;
        ilen = eil[b]; tlen = etl[b];
    } else {
        C = 64; S = 200;
        logits  = plog + (size_t)b * TMAX * 64;
        targets = ptgt + b * 200;
        ilen = pil[b]; tlen = ptl[b];
    }
    const int L    = 2 * S + 1;
    const int Teff = min(TMAX, max(ilen, 1));
    const int rlast = Teff - 1;

    // ---------- zero handshake ring (sentinel = lo32 == 0) ----------
    {
        uint4 z = make_uint4(0, 0, 0, 0);
        uint4* r4 = reinterpret_cast<uint4*>(sRing);
        for (int i = tid; i < 4 * TMAX / 2; i += NT) r4[i] = z;
    }

    // ---------- Phase 1: log2 softmax denominators ----------
    for (int t = tid; t < TMAX; t += NT) {
        if (t < Teff) {
            const float* row = logits + (size_t)t * C;
            float s = 0.f;
            for (int k = 0; k < C; k += 4) {
                float4 v = *reinterpret_cast<const float4*>(row + k);
                s += ex2(v.x * LOG2E) + ex2(v.y * LOG2E)
                   + ex2(v.z * LOG2E) + ex2(v.w * LOG2E);
            }
            sD[t] = lg2(s);
        } else {
            sD[t] = 0.f;
        }
    }
    __syncthreads();   // ring zeroed + sD ready; ONLY barrier before the scan

    // ---------- Per-thread slot setup: l = 4*tid + {0,1,2,3} ----------
    const int  l0 = 4 * tid;
    const bool v0 = (l0     < L), v1 = (l0 + 1 < L),
               v2 = (l0 + 2 < L), v3 = (l0 + 3 < L);
    const int  j1  = min(2 * tid,     S - 1);
    const int  j1m = max(2 * tid - 1, 0);
    const int  j3  = min(2 * tid + 1, S - 1);
    const int  ext1 = targets[j1];
    const int  ext3 = targets[j3];
    const bool skip1 = (tid >= 1) && (ext1 != targets[j1m]);
    const bool skip3 = (ext3 != ext1);

    // ---------- alpha init (t = 0) ----------
    float m0 = 1.f, m1 = 1.f, m2 = 1.f, m3 = 1.f;
    int   e0 = EDEAD, e1 = EDEAD, e2 = EDEAD, e3 = EDEAD;
    if (tid == 0) {
        float a = ex2(clamplp(fmaf(logits[0],    LOG2E, -sD[0])));
        int bb = __float_as_int(a);
        e0 = (bb >> 23) - 127; m0 = __int_as_float((bb & 0x007FFFFF) | 0x3F800000);
        a = ex2(clamplp(fmaf(logits[ext1], LOG2E, -sD[0])));
        bb = __float_as_int(a);
        e1 = (bb >> 23) - 127; m1 = __int_as_float((bb & 0x007FFFFF) | 0x3F800000);
    }

    // shared-space addresses for the handshake ring
    unsigned ringW = (unsigned)__cvta_generic_to_shared(&sRing[wid * TMAX]);        // + 8*t
    unsigned ringR = (unsigned)__cvta_generic_to_shared(&sRing[(wid - 1) * TMAX]);  // + 8*(t-1)

    // publish initial slot-3 state (t = 0)
    if (lane == 31) {
        asm volatile("st.volatile.shared.v2.u32 [%0], {%1,%2};"
                     :: "r"(ringW), "r"(__float_as_uint(m3)), "r"((unsigned)e3));
    }

    const bool warpLive = (128 * wid < L);

    if (warpLive && Teff > 1) {
        // ---------- prefetch pipeline (depth 3) ----------
        const float* pB = logits;            // blank column 0
        const float* pE1 = logits + ext1;
        const float* pE3 = logits + ext3;
        size_t rstep = (size_t)C;

        size_t r1 = (size_t)min(1, rlast) * rstep;
        size_t r2 = (size_t)min(2, rlast) * rstep;
        size_t r3 = (size_t)min(3, rlast) * rstep;
        float w1b = pB[r1], w11 = pE1[r1], w13 = pE3[r1];
        float xAb = pB[r2], xA1 = pE1[r2], xA3 = pE3[r2];
        float xBb = pB[r3], xB1 = pE1[r3], xB3 = pE3[r3];

        float D1 = sD[min(1, rlast)];
        float pb = ex2(clamplp(fmaf(w1b, LOG2E, -D1)));
        float p1 = ex2(clamplp(fmaf(w11, LOG2E, -D1)));
        float p3 = ex2(clamplp(fmaf(w13, LOG2E, -D1)));

        unsigned rw = ringW + 8;             // write slot for t
        unsigned rr = ringR;                 // read slot t-1

        for (int t = 1; t < Teff; ++t) {
            // probs for step t+1 from xA (row t+1, loaded 2 iterations ago)
            float Dn = sD[min(t + 1, rlast)];
            float pnb = ex2(clamplp(fmaf(xAb, LOG2E, -Dn)));
            float pn1 = ex2(clamplp(fmaf(xA1, LOG2E, -Dn)));
            float pn3 = ex2(clamplp(fmaf(xA3, LOG2E, -Dn)));
            xAb = xBb; xA1 = xB1; xA3 = xB3;
            size_t rn = (size_t)min(t + 3, rlast) * rstep;
            xBb = pB[rn]; xB1 = pE1[rn]; xB3 = pE3[rn];

            // neighbor old slot-3 via shuffle (lane0 patched from ring below)
            float nm3 = __shfl_up_sync(0xffffffffu, m3, 1);
            int   ne3 = __shfl_up_sync(0xffffffffu, e3, 1);

            // slot 3 first (no incoming dependency) -> publish ASAP
            float o3m; int o3e;
            upd3(m3, e3, m2, e2, m1, skip3 ? e1 : EDEAD, p3, o3m, o3e);
            o3e = v3 ? o3e : EDEAD;
            if (lane == 31) {
                asm volatile("st.volatile.shared.v2.u32 [%0], {%1,%2};"
                             :: "r"(rw), "r"(__float_as_uint(o3m)), "r"((unsigned)o3e));
            }

            if (lane == 0) {
                if (wid > 0) {
                    unsigned lo, hi;
                    do {
                        asm volatile("ld.volatile.shared.v2.u32 {%0,%1}, [%2];"
                                     : "=r"(lo), "=r"(hi) : "r"(rr));
                    } while (lo == 0u);
                    nm3 = __uint_as_float(lo); ne3 = (int)hi;
                } else { nm3 = 1.f; ne3 = EDEAD; }
            }

            float o0m, o1m, o2m; int o0e, o1e, o2e;
            upd2(m0, e0, nm3, ne3, pb, o0m, o0e);                          // blank
            upd3(m1, e1, m0, e0, nm3, skip1 ? ne3 : EDEAD, p1, o1m, o1e);  // sym
            upd2(m2, e2, m1, e1, pb, o2m, o2e);                            // blank

            m0 = o0m; e0 = v0 ? o0e : EDEAD;
            m1 = o1m; e1 = v1 ? o1e : EDEAD;
            m2 = o2m; e2 = v2 ? o2e : EDEAD;
            m3 = o3m; e3 = o3e;

            pb = pnb; p1 = pn1; p3 = pn3;
            rw += 8; rr += 8;
        }
    }

    // ---------- publish finals ----------
    sFm[l0] = m0;     sFe[l0] = e0;
    sFm[l0 + 1] = m1; sFe[l0 + 1] = e1;
    sFm[l0 + 2] = m2; sFe[l0 + 2] = e2;
    sFm[l0 + 3] = m3; sFe[l0 + 3] = e3;
    __syncthreads();

    // ---------- loss + fused deterministic reduction ----------
    if (tid == 0) {
        const int iL = 2 * tlen - 1, iB = 2 * tlen;
        int   eL = sFe[iL], eB = sFe[iB];
        float mL = sFm[iL], mB = sFm[iB];
        int   em = max(eL, eB);
        float ss = mL * pow2c(eL + 127 - em) + mB * pow2c(eB + 127 - em);
        float loss = -((float)em + lg2(ss)) * LN2;
        if (em < -(1 << 27)) loss = 0.f;      // unreachable => inf => zeroed
        if (!(loss <= 1e29f)) loss = 0.f;     // zero_infinity / NaN
        g_partial[blockIdx.x] = loss / (float)tlen * (1.0f / BATCH);
        __threadfence();
        unsigned tk = atomicAdd(&g_count, 1u);
        sLast = (tk == 63u);
    }
    __syncthreads();
    if (sLast && tid == 0) {
        __threadfence();
        float s = 0.f;
        #pragma unroll
        for (int i = 0; i < 64; ++i) {
            float v;
            asm volatile("ld.global.cg.f32 %0, [%1];" : "=f"(v) : "l"(g_partial + i));
            s += v;
        }
        out[0] = s;
        g_count = 0;   // reset for graph replay
    }
}

extern "C" void kernel_launch(void* const* d_in, const int* in_sizes, int n_in,
                              void* d_out, int out_size)
{
    const float* elog = (const float*)d_in[0];
    const float* plog = (const float*)d_in[1];
    const int*   etgt = (const int*)d_in[2];
    const int*   ptgt = (const int*)d_in[3];
    const int*   eil  = (const int*)d_in[4];
    const int*   pil  = (const int*)d_in[5];
    const int*   etl  = (const int*)d_in[6];
    const int*   ptl  = (const int*)d_in[7];
    float* out = (float*)d_out;

    cudaFuncSetAttribute(ctc_forward_kernel,
                         cudaFuncAttributeMaxDynamicSharedMemorySize, DYNSMEM);
    ctc_forward_kernel<<<64, NT, DYNSMEM>>>(elog, plog, etgt, ptgt,
                                            eil, pil, etl, ptl, out);
}

// round 11
// speedup vs baseline: 1.7182x; 1.7182x over previous
#include <cuda_runtime.h>
#include <cuda_bf16.h>

// CTC forward, two tasks (PyTorch semantics: blank=0, mean of loss/target_len,
// zero_infinity). One block per (task, batch) = 64 blocks x 128 threads.
//
// Register-blocked wavefront: 4 extended-target slots per thread as
// (mantissa in [1,2), int32 exponent) pairs; no MUFU on the critical path.
// TWO timesteps per __syncthreads(): cross-warp operand for the second step is
// obtained by lane0 redundantly simulating the left warp's lane31 slot-3 update
// from a state record published at the previous barrier.

#define LOG2E 1.4426950408889634f
#define LN2   0.6931471805599453f
#define BATCH 32
#define TMAX  2000
#define NT    128
#define EDEAD (-(1 << 28))

static __device__ float        g_partial[64];
static __device__ unsigned int g_count = 0;

__device__ __forceinline__ float ex2(float x) {
    float y; asm("ex2.approx.f32 %0, %1;" : "=f"(y) : "f"(x)); return y;
}
__device__ __forceinline__ float lg2(float x) {
    float y; asm("lg2.approx.f32 %0, %1;" : "=f"(y) : "f"(x)); return y;
}

__device__ __forceinline__ void upd3(float ma, int ea, float mb, int eb,
                                     float mc, int ec, float p,
                                     float& mo, int& eo) {
    int em = max(ea, max(eb, ec));
    float sa = __int_as_float(max(ea - em + 127, 0) << 23);
    float sb = __int_as_float(max(eb - em + 127, 0) << 23);
    float sc = __int_as_float(max(ec - em + 127, 0) << 23);
    float s  = fmaf(mc, sc, fmaf(mb, sb, ma * sa));   // [1,6)
    float mp = p * s;                                  // normal, >0
    int bb = __float_as_int(mp);
    eo = em + ((bb >> 23) - 127);
    mo = __int_as_float((bb & 0x007FFFFF) | 0x3F800000);
}
__device__ __forceinline__ void upd2(float ma, int ea, float mb, int eb,
                                     float p, float& mo, int& eo) {
    int em = max(ea, eb);
    float sa = __int_as_float(max(ea - em + 127, 0) << 23);
    float sb = __int_as_float(max(eb - em + 127, 0) << 23);
    float s  = fmaf(mb, sb, ma * sa);
    float mp = p * s;
    int bb = __float_as_int(mp);
    eo = em + ((bb >> 23) - 127);
    mo = __int_as_float((bb & 0x007FFFFF) | 0x3F800000);
}
__device__ __forceinline__ float pow2c(int dp127) {
    return __int_as_float(max(dp127, 0) << 23);
}
__device__ __forceinline__ float clamplp(float x) {   // keep ex2 output normal
    return fminf(fmaxf(x, -120.f), 0.f);
}

__global__ void __launch_bounds__(NT, 1)
ctc_forward_kernel(const float* __restrict__ elog, const float* __restrict__ plog,
                   const int* __restrict__ etgt, const int* __restrict__ ptgt,
                   const int* __restrict__ eil,  const int* __restrict__ pil,
                   const int* __restrict__ etl,  const int* __restrict__ ptl,
                   float* __restrict__ out)
{
    __shared__ float sD[TMAX];        // log2 softmax denominator per timestep
    __shared__ float sStage[4][64];   // 4-deep ring of staged log2-prob rows
    __shared__ uint4 sBndA[2][4];     // {m1,e1,m2,e2} per warp, double-buffered
    __shared__ uint2 sBndB[2][4];     // {m3,e3}
    __shared__ float sFm[NT * 4];
    __shared__ int   sFe[NT * 4];
    __shared__ int   sLast;

    const int task = blockIdx.x >> 5;   // 0 = error (C=4), 1 = phoneme (C=64)
    const int b    = blockIdx.x & 31;
    const int tid  = threadIdx.x;
    const int lane = tid & 31;
    const int wid  = tid >> 5;

    const float* logits;
    const int*   targets;
    int C, S, ilen, tlen;
    if (task == 0) {
        C = 4;  S = 50;
        logits  = elog + (size_t)b * TMAX * 4;
        targets = etgt + b * 50;
        ilen = eil[b]; tlen = etl[b];
    } else {
        C = 64; S = 200;
        logits  = plog + (size_t)b * TMAX * 64;
        targets = ptgt + b * 200;
        ilen = pil[b]; tlen = ptl[b];
    }
    const int L     = 2 * S + 1;
    const int Teff  = min(TMAX, max(ilen, 1));
    const int rlast = Teff - 1;

    // ---------- Phase 1: log2 softmax denominators ----------
    for (int t = tid; t < Teff; t += NT) {
        const float* row = logits + (size_t)t * C;
        float s = 0.f;
        for (int k = 0; k < C; k += 4) {
            float4 v = *reinterpret_cast<const float4*>(row + k);
            s += ex2(v.x * LOG2E) + ex2(v.y * LOG2E)
               + ex2(v.z * LOG2E) + ex2(v.w * LOG2E);
        }
        sD[t] = lg2(s);
    }
    __syncthreads();

    // ---------- Per-thread slot setup: l = 4*tid + {0,1,2,3} ----------
    const int  l0 = 4 * tid;
    const int  j1  = min(2 * tid,     S - 1);
    const int  j1m = max(2 * tid - 1, 0);
    const int  j3  = min(2 * tid + 1, S - 1);
    const int  ext1 = targets[j1];
    const int  ext3 = targets[j3];
    const bool skip1 = (tid >= 1) && (ext1 != targets[j1m]);
    const bool skip3 = (ext3 != ext1);

    // Left-neighbor metadata (for lane0's slot-3 simulation).
    int  lext3 = ext3;
    bool lskip3 = false;
    if (lane == 0 && wid > 0) {
        int j1L = min(2 * tid - 2, S - 1);
        int j3L = min(2 * tid - 1, S - 1);
        lext3  = targets[j3L];
        lskip3 = (targets[j3L] != targets[j1L]);
    }

    // ---------- alpha init (t = 0) ----------
    float m0 = 1.f, m1 = 1.f, m2 = 1.f, m3 = 1.f;
    int   e0 = EDEAD, e1 = EDEAD, e2 = EDEAD, e3 = EDEAD;
    if (tid == 0) {
        float a = ex2(clamplp(fmaf(logits[0],    LOG2E, -sD[0])));
        int bb = __float_as_int(a);
        e0 = (bb >> 23) - 127; m0 = __int_as_float((bb & 0x007FFFFF) | 0x3F800000);
        a = ex2(clamplp(fmaf(logits[ext1], LOG2E, -sD[0])));
        bb = __float_as_int(a);
        e1 = (bb >> 23) - 127; m1 = __int_as_float((bb & 0x007FFFFF) | 0x3F800000);
    }
    if (lane == 31) {
        sBndA[0][wid] = make_uint4(__float_as_uint(m1), (unsigned)e1,
                                   __float_as_uint(m2), (unsigned)e2);
        sBndB[0][wid] = make_uint2(__float_as_uint(m3), (unsigned)e3);
    }

    // Stage rows 1,2 into ring buffers 1,2; prefetch rows 3,4.
    float gA = 0.f, gB = 0.f;
    if (tid < C) {
        sStage[1][tid] = fmaf(logits[(size_t)min(1, rlast) * C + tid], LOG2E,
                              -sD[min(1, rlast)]);
        sStage[2][tid] = fmaf(logits[(size_t)min(2, rlast) * C + tid], LOG2E,
                              -sD[min(2, rlast)]);
        gA = logits[(size_t)min(3, rlast) * C + tid];
        gB = logits[(size_t)min(4, rlast) * C + tid];
    }
    __syncthreads();

    // ---------- Phase 2: forward scan, 2 steps per barrier ----------
    for (int t = 1; t < Teff; t += 2) {
        const int  rp  = ((t - 1) >> 1) & 1;
        const int  wq  = rp ^ 1;
        const bool two = (t + 1 < Teff);

        // lane0: left warp's lane31 state @ t-1
        float lm1 = 1.f, lm2 = 1.f, lm3 = 1.f;
        int   le1 = EDEAD, le2 = EDEAD, le3 = EDEAD;
        if (lane == 0 && wid > 0) {
            uint4 av = sBndA[rp][wid - 1];
            uint2 bv = sBndB[rp][wid - 1];
            lm1 = __uint_as_float(av.x); le1 = (int)av.y;
            lm2 = __uint_as_float(av.z); le2 = (int)av.w;
            lm3 = __uint_as_float(bv.x); le3 = (int)bv.y;
        }

        // probs for steps t (row ring t&3) and t+1 (ring (t+1)&3)
        const float* rowT  = sStage[t & 3];
        const float* rowT1 = sStage[(t + 1) & 3];
        float pb  = ex2(clamplp(rowT[0]));
        float p1  = ex2(clamplp(rowT[ext1]));
        float p3  = ex2(clamplp(rowT[ext3]));
        float lp3 = ex2(clamplp(rowT[lext3]));   // neighbor's p3 @ step t
        float qb  = ex2(clamplp(rowT1[0]));
        float q1  = ex2(clamplp(rowT1[ext1]));
        float q3  = ex2(clamplp(rowT1[ext3]));

        // stage rows t+2, t+3; prefetch rows t+4, t+5
        if (tid < C) {
            sStage[(t + 2) & 3][tid] = fmaf(gA, LOG2E, -sD[min(t + 2, rlast)]);
            sStage[(t + 3) & 3][tid] = fmaf(gB, LOG2E, -sD[min(t + 3, rlast)]);
            gA = logits[(size_t)min(t + 4, rlast) * C + tid];
            gB = logits[(size_t)min(t + 5, rlast) * C + tid];
        }

        // ---- step t ----
        float nm3 = __shfl_up_sync(0xffffffffu, m3, 1);
        int   ne3 = __shfl_up_sync(0xffffffffu, e3, 1);
        if (lane == 0) {
            if (wid > 0) { nm3 = lm3; ne3 = le3; }
            else         { nm3 = 1.f; ne3 = EDEAD; }
        }

        float a0m, a1m, a2m, a3m; int a0e, a1e, a2e, a3e;
        upd2(m0, e0, nm3, ne3, pb, a0m, a0e);
        upd3(m1, e1, m0, e0, nm3, skip1 ? ne3 : EDEAD, p1, a1m, a1e);
        upd2(m2, e2, m1, e1, pb, a2m, a2e);
        upd3(m3, e3, m2, e2, m1, skip3 ? e1 : EDEAD, p3, a3m, a3e);

        // lane0: simulate left lane31's slot-3 @ t (internal-only update)
        float sm3 = 1.f; int se3 = EDEAD;
        if (lane == 0 && wid > 0) {
            upd3(lm3, le3, lm2, le2, lm1, lskip3 ? le1 : EDEAD, lp3, sm3, se3);
        }

        m0 = a0m; e0 = a0e; m1 = a1m; e1 = a1e;
        m2 = a2m; e2 = a2e; m3 = a3m; e3 = a3e;

        // ---- step t+1 ----
        if (two) {
            float nb = __shfl_up_sync(0xffffffffu, m3, 1);
            int   ne = __shfl_up_sync(0xffffffffu, e3, 1);
            if (lane == 0) {
                if (wid > 0) { nb = sm3; ne = se3; }
                else         { nb = 1.f; ne = EDEAD; }
            }
            upd2(m0, e0, nb, ne, qb, a0m, a0e);
            upd3(m1, e1, m0, e0, nb, skip1 ? ne : EDEAD, q1, a1m, a1e);
            upd2(m2, e2, m1, e1, qb, a2m, a2e);
            upd3(m3, e3, m2, e2, m1, skip3 ? e1 : EDEAD, q3, a3m, a3e);
            m0 = a0m; e0 = a0e; m1 = a1m; e1 = a1e;
            m2 = a2m; e2 = a2e; m3 = a3m; e3 = a3e;
        }

        if (lane == 31) {
            sBndA[wq][wid] = make_uint4(__float_as_uint(m1), (unsigned)e1,
                                        __float_as_uint(m2), (unsigned)e2);
            sBndB[wq][wid] = make_uint2(__float_as_uint(m3), (unsigned)e3);
        }
        __syncthreads();
    }

    // ---------- publish finals ----------
    sFm[l0] = m0;     sFe[l0] = e0;
    sFm[l0 + 1] = m1; sFe[l0 + 1] = e1;
    sFm[l0 + 2] = m2; sFe[l0 + 2] = e2;
    sFm[l0 + 3] = m3; sFe[l0 + 3] = e3;
    __syncthreads();

    // ---------- loss + fused deterministic reduction ----------
    if (tid == 0) {
        const int iL = 2 * tlen - 1, iB = 2 * tlen;
        int   eL = sFe[iL], eB = sFe[iB];
        float mL = sFm[iL], mB = sFm[iB];
        int   em = max(eL, eB);
        float ss = mL * pow2c(eL + 127 - em) + mB * pow2c(eB + 127 - em);
        float loss = -((float)em + lg2(ss)) * LN2;
        if (em < -(1 << 27)) loss = 0.f;      // unreachable => inf => zeroed
        if (!(loss <= 1e29f)) loss = 0.f;     // zero_infinity / NaN
        g_partial[blockIdx.x] = loss / (float)tlen * (1.0f / BATCH);
        __threadfence();
        unsigned tk = atomicAdd(&g_count, 1u);
        sLast = (tk == 63u);
    }
    __syncthreads();
    if (sLast && tid == 0) {
        __threadfence();
        float s = 0.f;
        #pragma unroll
        for (int i = 0; i < 64; ++i) {
            float v;
            asm volatile("ld.global.cg.f32 %0, [%1];" : "=f"(v) : "l"(g_partial + i));
            s += v;
        }
        out[0] = s;
        g_count = 0;   // reset for graph replay
    }
}

extern "C" void kernel_launch(void* const* d_in, const int* in_sizes, int n_in,
                              void* d_out, int out_size)
{
    const float* elog = (const float*)d_in[0];
    const float* plog = (const float*)d_in[1];
    const int*   etgt = (const int*)d_in[2];
    const int*   ptgt = (const int*)d_in[3];
    const int*   eil  = (const int*)d_in[4];
    const int*   pil  = (const int*)d_in[5];
    const int*   etl  = (const int*)d_in[6];
    const int*   ptl  = (const int*)d_in[7];
    float* out = (float*)d_out;

    ctc_forward_kernel<<<64, NT>>>(elog, plog, etgt, ptgt,
                                   eil, pil, etl, ptl, out);
}